// round 5
// baseline (speedup 1.0000x reference)
#include <cuda_runtime.h>
#include <cuda_bf16.h>

// Problem constants
#define T_LEN   1024
#define PP      16
#define HID     10

#define L2E  1.442695040888963f   // log2(e)

// Scratch (device globals: allocation-free rule)
// padded by 32 float4 so depth-3 prefetch (+unroll lookahead) never reads OOB
__device__ float4 g_preNF[T_LEN * HID + 64];          // node forward  SCALED(Wih@x+b), (i,f,g,o)
__device__ float4 g_preEF[PP * T_LEN * HID + 64];     // edge forward
__device__ float4 g_preEB[PP * T_LEN * HID + 64];     // edge backward, stored TIME-REVERSED per person

// ---------- packed f32x2 helpers ----------
__device__ __forceinline__ unsigned long long pack2(float lo, float hi) {
    unsigned long long r;
    asm("mov.b64 %0, {%1, %2};" : "=l"(r) : "f"(lo), "f"(hi));
    return r;
}
__device__ __forceinline__ void unpack2(unsigned long long v, float& lo, float& hi) {
    asm("mov.b64 {%0, %1}, %2;" : "=f"(lo), "=f"(hi) : "l"(v));
}
__device__ __forceinline__ void fma2(unsigned long long& d, unsigned long long a, unsigned long long b) {
    asm("fma.rn.f32x2 %0, %1, %2, %0;" : "+l"(d) : "l"(a), "l"(b));
}
__device__ __forceinline__ unsigned long long add2(unsigned long long a, unsigned long long b) {
    unsigned long long r;
    asm("add.rn.f32x2 %0, %1, %2;" : "=l"(r) : "l"(a), "l"(b));
    return r;
}
__device__ __forceinline__ float ex2_(float x) {
    float r; asm("ex2.approx.f32 %0, %1;" : "=f"(r) : "f"(x)); return r;
}
__device__ __forceinline__ float rcp_(float x) {
    float r; asm("rcp.approx.f32 %0, %1;" : "=f"(r) : "f"(x)); return r;
}

// One LSTM step with PRE-SCALED gate inputs:
//   gi,gf,go accumulate  -log2e * a   (so sigmoid(a) = rcp(1 + ex2(gi)))
//   gg accumulates       2*log2e * a  (so tanh(a)    = 1 - 2*rcp(1 + ex2(gg)))
// Lane j holds hidden unit j (lanes >= 10 run clamped garbage, never read).
__device__ __forceinline__ void lstm_step(float& h, float& c, float4 pre,
                                          const unsigned long long* Wif,
                                          const unsigned long long* Wgo) {
    // Interleaved shfl issue order: chains A (k=0..4) and B (k=5..9) both get
    // operands at 2*rt spacing regardless of SHFL reciprocal throughput.
    float hk[HID];
    hk[0] = __shfl_sync(0xffffffffu, h, 0);
    hk[5] = __shfl_sync(0xffffffffu, h, 5);
    hk[1] = __shfl_sync(0xffffffffu, h, 1);
    hk[6] = __shfl_sync(0xffffffffu, h, 6);
    hk[2] = __shfl_sync(0xffffffffu, h, 2);
    hk[7] = __shfl_sync(0xffffffffu, h, 7);
    hk[3] = __shfl_sync(0xffffffffu, h, 3);
    hk[8] = __shfl_sync(0xffffffffu, h, 8);
    hk[4] = __shfl_sync(0xffffffffu, h, 4);
    hk[9] = __shfl_sync(0xffffffffu, h, 9);

    unsigned long long aif0 = pack2(pre.x, pre.y);   // (i, f) chain A
    unsigned long long ago0 = pack2(pre.z, pre.w);   // (g, o) chain A
    unsigned long long aif1 = pack2(0.0f, 0.0f);     // chain B
    unsigned long long ago1 = pack2(0.0f, 0.0f);
#pragma unroll
    for (int k = 0; k < 5; k++) {
        unsigned long long hhA = pack2(hk[k], hk[k]);
        unsigned long long hhB = pack2(hk[k + 5], hk[k + 5]);
        fma2(aif0, Wif[k], hhA);
        fma2(ago0, Wgo[k], hhA);
        fma2(aif1, Wif[k + 5], hhB);
        fma2(ago1, Wgo[k + 5], hhB);
    }
    float gi, gf, gg, go;
    unpack2(add2(aif0, aif1), gi, gf);
    unpack2(add2(ago0, ago1), gg, go);

    float ri = rcp_(1.0f + ex2_(gi));     // i = sigmoid(ai)
    float rf = rcp_(1.0f + ex2_(gf));     // f
    float rg = rcp_(1.0f + ex2_(gg));     // tanh(ag) = 1 - 2*rg
    float ro = rcp_(1.0f + ex2_(go));     // o
    float m2i = -2.0f * ri;               // off-chain (i ready before g)
    float ig  = fmaf(m2i, rg, ri);        // i * tanh(ag)
    c = fmaf(rf, c, ig);
    float ec = ex2_(c * (2.0f * L2E));    // exp(2c)
    float rc = rcp_(1.0f + ec);
    float m2o = -2.0f * ro;               // off-chain (o ready while ec/rc in flight)
    h = fmaf(m2o, rc, ro);                // o * tanh(c)
}

// ---------- kernel 1: parallel precompute of SCALED (Wih@x + b) for all steps ----------
__global__ void precompute_kernel(const float* __restrict__ x,     // [T,2]
                                  const float* __restrict__ oth,   // [P,T,2]
                                  const float* __restrict__ nWihF, // [40,2]
                                  const float* __restrict__ nbF,   // [40]
                                  const float* __restrict__ eWihF, // [40,4]
                                  const float* __restrict__ ebF,   // [40]
                                  const float* __restrict__ eWihB, // [40,4]
                                  const float* __restrict__ ebB)   // [40]
{
    int gid = blockIdx.x * blockDim.x + threadIdx.x;
    const int NNF = T_LEN * HID;
    const int NE  = PP * T_LEN * HID;
    if (gid < NNF) {
        int t = gid / HID, j = gid % HID;
        float x0 = x[2 * t], x1 = x[2 * t + 1];
        float v[4];
#pragma unroll
        for (int gI = 0; gI < 4; gI++) {
            int row = gI * HID + j;
            v[gI] = fmaf(nWihF[row * 2], x0, fmaf(nWihF[row * 2 + 1], x1, nbF[row]));
        }
        g_preNF[gid] = make_float4(-L2E * v[0], -L2E * v[1], 2.0f * L2E * v[2], -L2E * v[3]);
    } else if (gid < NNF + 2 * NE) {
        int e = gid - NNF;
        bool isB = (e >= NE);
        if (isB) e -= NE;
        int j = e % HID;
        int t = (e / HID) % T_LEN;
        int p = e / (T_LEN * HID);
        float x0 = x[2 * t], x1 = x[2 * t + 1];
        float x2 = oth[(p * T_LEN + t) * 2], x3 = oth[(p * T_LEN + t) * 2 + 1];
        const float* W = isB ? eWihB : eWihF;
        const float* b = isB ? ebB : ebF;
        float v[4];
#pragma unroll
        for (int gI = 0; gI < 4; gI++) {
            int row = gI * HID + j;
            v[gI] = fmaf(W[row * 4 + 0], x0,
                    fmaf(W[row * 4 + 1], x1,
                    fmaf(W[row * 4 + 2], x2,
                    fmaf(W[row * 4 + 3], x3, b[row]))));
        }
        float4 sv = make_float4(-L2E * v[0], -L2E * v[1], 2.0f * L2E * v[2], -L2E * v[3]);
        if (isB) {
            // store time-reversed so the backward chain streams linearly
            int tstore = (T_LEN - 1) - t;
            g_preEB[(p * T_LEN + tstore) * HID + j] = sv;
        } else {
            g_preEF[(p * T_LEN + t) * HID + j] = sv;
        }
    }
}

// ---------- kernel 2: 4 sequential chains, one warp each (4 distinct SMSPs) ----------
__global__ void __launch_bounds__(128, 1) seq_kernel(
    const float* __restrict__ x,
    const float* __restrict__ nWhhF, const float* __restrict__ nWhhB,
    const float* __restrict__ nWihB, const float* __restrict__ nbB,
    const float* __restrict__ eWhhF, const float* __restrict__ eWhhB,
    const float* __restrict__ linW, const float* __restrict__ linb,
    float* __restrict__ out)
{
    __shared__ float sh[4][HID]; // 0=edgeF final, 1=edgeB first-of-p15, 2=nodeF final, 3=nodeB first

    int tid = threadIdx.x;
    int w = tid >> 5, lane = tid & 31;
    int j = lane < HID ? lane : HID - 1;  // clamp: lanes 10..31 compute harmless garbage

    // Recurrent weights for this chain, packed with gate-scales folded in:
    // rows i,f,o get -log2e; row g gets +2*log2e. Whh row-major [4H][H].
    const float* Whh = (w == 0) ? eWhhF : (w == 1) ? eWhhB : (w == 2) ? nWhhF : nWhhB;
    unsigned long long Wif[HID], Wgo[HID];
#pragma unroll
    for (int k = 0; k < HID; k++) {
        Wif[k] = pack2(-L2E * Whh[(0 * HID + j) * HID + k],
                       -L2E * Whh[(1 * HID + j) * HID + k]);
        Wgo[k] = pack2(2.0f * L2E * Whh[(2 * HID + j) * HID + k],
                       -L2E * Whh[(3 * HID + j) * HID + k]);
    }

    float h = 0.0f, c = 0.0f;

    if (w < 3) {
        const float4* pre;
        int N;
        if (w == 0)      { pre = g_preEF; N = PP * T_LEN; }           // 16384 steps
        else if (w == 1) { pre = g_preEB; N = (PP - 1) * T_LEN + 1; } // 15361 steps (p0..14 full + 1 step of p15)
        else             { pre = g_preNF; N = T_LEN; }                // 1024 steps

        // depth-3 software prefetch: load for step s+3 issues during step s
        // (3 x ~140cyc covers the 262cyc far-die L2 latency with margin).
        // unroll 2: halves loop bookkeeping / buffer-rotation overhead; the
        // compiler handles the odd trip count (15361) remainder.
        const float4* p0 = pre + j;
        float4 b0 = p0[0];
        float4 b1 = p0[HID];
        float4 b2 = p0[2 * HID];
        p0 += 3 * HID;
#pragma unroll 2
        for (int s = 0; s < N; s++) {
            float4 b3 = p0[0];
            p0 += HID;
            lstm_step(h, c, b0, Wif, Wgo);
            b0 = b1;
            b1 = b2;
            b2 = b3;
        }
    } else {
        // node backward: single step from zero state on x[T-1]
        float x0 = x[2 * (T_LEN - 1)], x1 = x[2 * (T_LEN - 1) + 1];
        float v0 = fmaf(nWihB[(0 * HID + j) * 2], x0, fmaf(nWihB[(0 * HID + j) * 2 + 1], x1, nbB[0 * HID + j]));
        float v1 = fmaf(nWihB[(1 * HID + j) * 2], x0, fmaf(nWihB[(1 * HID + j) * 2 + 1], x1, nbB[1 * HID + j]));
        float v2 = fmaf(nWihB[(2 * HID + j) * 2], x0, fmaf(nWihB[(2 * HID + j) * 2 + 1], x1, nbB[2 * HID + j]));
        float v3 = fmaf(nWihB[(3 * HID + j) * 2], x0, fmaf(nWihB[(3 * HID + j) * 2 + 1], x1, nbB[3 * HID + j]));
        float4 pv = make_float4(-L2E * v0, -L2E * v1, 2.0f * L2E * v2, -L2E * v3);
        lstm_step(h, c, pv, Wif, Wgo);
    }

    if (lane < HID) sh[w][lane] = h;
    __syncthreads();

    // tag[m] = lin_b[m] + sum_k (node+edge)[k] * lin_W[m][k]; only last timestep matters
    if (tid < 2) {
        float acc = linb[tid];
#pragma unroll
        for (int k = 0; k < HID; k++) {
            acc = fmaf(sh[2][k] + sh[0][k], linW[tid * 2 * HID + k], acc);          // forward halves
            acc = fmaf(sh[3][k] + sh[1][k], linW[tid * 2 * HID + HID + k], acc);    // backward halves
        }
        out[tid] = acc;
    }
}

extern "C" void kernel_launch(void* const* d_in, const int* in_sizes, int n_in,
                              void* d_out, int out_size) {
    const float* x     = (const float*)d_in[0];   // self_pose  [1,T,2]
    const float* oth   = (const float*)d_in[1];   // others_pose [1,P,T,2]
    const float* nWihF = (const float*)d_in[2];
    const float* nWhhF = (const float*)d_in[3];
    const float* nbF   = (const float*)d_in[4];
    const float* nWihB = (const float*)d_in[5];
    const float* nWhhB = (const float*)d_in[6];
    const float* nbB   = (const float*)d_in[7];
    const float* eWihF = (const float*)d_in[8];
    const float* eWhhF = (const float*)d_in[9];
    const float* ebF   = (const float*)d_in[10];
    const float* eWihB = (const float*)d_in[11];
    const float* eWhhB = (const float*)d_in[12];
    const float* ebB   = (const float*)d_in[13];
    const float* linW  = (const float*)d_in[14];
    const float* linb  = (const float*)d_in[15];

    int total = T_LEN * HID + 2 * PP * T_LEN * HID;
    precompute_kernel<<<(total + 255) / 256, 256>>>(x, oth, nWihF, nbF, eWihF, ebF, eWihB, ebB);
    seq_kernel<<<1, 128>>>(x, nWhhF, nWhhB, nWihB, nbB, eWhhF, eWhhB, linW, linb, (float*)d_out);
}

// round 6
// speedup vs baseline: 1.2330x; 1.2330x over previous
#include <cuda_runtime.h>
#include <cuda_bf16.h>

// Problem constants
#define T_LEN   1024
#define PP      16
#define HID     10

// Scratch (device globals: allocation-free rule)
// padded by 64 float4 so depth-3 prefetch (+unroll lookahead) never reads OOB
__device__ float4 g_preNF[T_LEN * HID + 64];          // node forward  SCALED(Wih@x+b), (i,f,g,o)
__device__ float4 g_preEF[PP * T_LEN * HID + 64];     // edge forward
__device__ float4 g_preEB[PP * T_LEN * HID + 64];     // edge backward, stored TIME-REVERSED per person

// ---------- packed f32x2 helpers ----------
__device__ __forceinline__ unsigned long long pack2(float lo, float hi) {
    unsigned long long r;
    asm("mov.b64 %0, {%1, %2};" : "=l"(r) : "f"(lo), "f"(hi));
    return r;
}
__device__ __forceinline__ void unpack2(unsigned long long v, float& lo, float& hi) {
    asm("mov.b64 {%0, %1}, %2;" : "=f"(lo), "=f"(hi) : "l"(v));
}
__device__ __forceinline__ void fma2(unsigned long long& d, unsigned long long a, unsigned long long b) {
    asm("fma.rn.f32x2 %0, %1, %2, %0;" : "+l"(d) : "l"(a), "l"(b));
}
__device__ __forceinline__ unsigned long long add2(unsigned long long a, unsigned long long b) {
    unsigned long long r;
    asm("add.rn.f32x2 %0, %1, %2;" : "=l"(r) : "l"(a), "l"(b));
    return r;
}
__device__ __forceinline__ float tanh_(float x) {
    float r; asm("tanh.approx.f32 %0, %1;" : "=f"(r) : "f"(x)); return r;
}

// One LSTM step with PRE-SCALED gate inputs:
//   i,f,o gates accumulate a/2  (sigmoid(a) = 0.5 + 0.5*tanh(a/2), MUFU.TANH)
//   g gate accumulates a        (tanh(a) direct)
// Lane j holds hidden unit j (lanes >= 10 run clamped garbage, never read).
// h-broadcast via shared memory: STS + warpsync + 3 vector LDS
// (4 MIO ops, fixed ~60cyc to all operands; replaces 10 variable-lat SHFLs).
__device__ __forceinline__ void lstm_step(float& h, float& c, float4 pre,
                                          const unsigned long long* Wif,
                                          const unsigned long long* Wgo,
                                          volatile float* shb, int lane) {
    if (lane < HID) shb[lane] = h;
    __syncwarp();
    float4 hA = *(const float4*)(shb);       // h0..h3
    float4 hB = *(const float4*)(shb + 4);   // h4..h7
    float2 hC = *(const float2*)(shb + 8);   // h8, h9

    unsigned long long aif0 = pack2(pre.x, pre.y);   // (i, f) chain A
    unsigned long long ago0 = pack2(pre.z, pre.w);   // (g, o) chain A
    unsigned long long aif1 = pack2(0.0f, 0.0f);     // chain B (5-deep split halves dep chain)
    unsigned long long ago1 = pack2(0.0f, 0.0f);

    unsigned long long h0 = pack2(hA.x, hA.x), h1 = pack2(hA.y, hA.y);
    unsigned long long h2 = pack2(hA.z, hA.z), h3 = pack2(hA.w, hA.w);
    unsigned long long h4 = pack2(hB.x, hB.x), h5 = pack2(hB.y, hB.y);
    unsigned long long h6 = pack2(hB.z, hB.z), h7 = pack2(hB.w, hB.w);
    unsigned long long h8 = pack2(hC.x, hC.x), h9 = pack2(hC.y, hC.y);

    fma2(aif0, Wif[0], h0);  fma2(ago0, Wgo[0], h0);
    fma2(aif1, Wif[5], h5);  fma2(ago1, Wgo[5], h5);
    fma2(aif0, Wif[1], h1);  fma2(ago0, Wgo[1], h1);
    fma2(aif1, Wif[6], h6);  fma2(ago1, Wgo[6], h6);
    fma2(aif0, Wif[2], h2);  fma2(ago0, Wgo[2], h2);
    fma2(aif1, Wif[7], h7);  fma2(ago1, Wgo[7], h7);
    fma2(aif0, Wif[3], h3);  fma2(ago0, Wgo[3], h3);
    fma2(aif1, Wif[8], h8);  fma2(ago1, Wgo[8], h8);
    fma2(aif0, Wif[4], h4);  fma2(ago0, Wgo[4], h4);
    fma2(aif1, Wif[9], h9);  fma2(ago1, Wgo[9], h9);

    float gi, gf, gg, go;
    unpack2(add2(aif0, aif1), gi, gf);
    unpack2(add2(ago0, ago1), gg, go);

    // MUFU.TANH activations (g first: it's needed earliest)
    float tg = tanh_(gg);
    float ti = tanh_(gi);
    float tf = tanh_(gf);
    float to = tanh_(go);
    float i = fmaf(ti, 0.5f, 0.5f);
    float f = fmaf(tf, 0.5f, 0.5f);
    float o = fmaf(to, 0.5f, 0.5f);
    float ig = i * tg;
    c = fmaf(f, c, ig);
    float tc = tanh_(c);
    h = o * tc;
}

// ---------- kernel 1: parallel precompute of SCALED (Wih@x + b) for all steps ----------
// gate scales: i,f,o rows x0.5 (sigmoid-from-tanh), g row x1.0
__global__ void precompute_kernel(const float* __restrict__ x,     // [T,2]
                                  const float* __restrict__ oth,   // [P,T,2]
                                  const float* __restrict__ nWihF, // [40,2]
                                  const float* __restrict__ nbF,   // [40]
                                  const float* __restrict__ eWihF, // [40,4]
                                  const float* __restrict__ ebF,   // [40]
                                  const float* __restrict__ eWihB, // [40,4]
                                  const float* __restrict__ ebB)   // [40]
{
    int gid = blockIdx.x * blockDim.x + threadIdx.x;
    const int NNF = T_LEN * HID;
    const int NE  = PP * T_LEN * HID;
    if (gid < NNF) {
        int t = gid / HID, j = gid % HID;
        float x0 = x[2 * t], x1 = x[2 * t + 1];
        float v[4];
#pragma unroll
        for (int gI = 0; gI < 4; gI++) {
            int row = gI * HID + j;
            v[gI] = fmaf(nWihF[row * 2], x0, fmaf(nWihF[row * 2 + 1], x1, nbF[row]));
        }
        g_preNF[gid] = make_float4(0.5f * v[0], 0.5f * v[1], v[2], 0.5f * v[3]);
    } else if (gid < NNF + 2 * NE) {
        int e = gid - NNF;
        bool isB = (e >= NE);
        if (isB) e -= NE;
        int j = e % HID;
        int t = (e / HID) % T_LEN;
        int p = e / (T_LEN * HID);
        float x0 = x[2 * t], x1 = x[2 * t + 1];
        float x2 = oth[(p * T_LEN + t) * 2], x3 = oth[(p * T_LEN + t) * 2 + 1];
        const float* W = isB ? eWihB : eWihF;
        const float* b = isB ? ebB : ebF;
        float v[4];
#pragma unroll
        for (int gI = 0; gI < 4; gI++) {
            int row = gI * HID + j;
            v[gI] = fmaf(W[row * 4 + 0], x0,
                    fmaf(W[row * 4 + 1], x1,
                    fmaf(W[row * 4 + 2], x2,
                    fmaf(W[row * 4 + 3], x3, b[row]))));
        }
        float4 sv = make_float4(0.5f * v[0], 0.5f * v[1], v[2], 0.5f * v[3]);
        if (isB) {
            // store time-reversed so the backward chain streams linearly
            int tstore = (T_LEN - 1) - t;
            g_preEB[(p * T_LEN + tstore) * HID + j] = sv;
        } else {
            g_preEF[(p * T_LEN + t) * HID + j] = sv;
        }
    }
}

// ---------- kernel 2: 4 sequential chains, one warp each (4 distinct SMSPs) ----------
__global__ void __launch_bounds__(128, 1) seq_kernel(
    const float* __restrict__ x,
    const float* __restrict__ nWhhF, const float* __restrict__ nWhhB,
    const float* __restrict__ nWihB, const float* __restrict__ nbB,
    const float* __restrict__ eWhhF, const float* __restrict__ eWhhB,
    const float* __restrict__ linW, const float* __restrict__ linb,
    float* __restrict__ out)
{
    __shared__ __align__(16) float shH[4][16];  // per-warp h broadcast buffer
    __shared__ float sh[4][HID]; // final h: 0=edgeF, 1=edgeB, 2=nodeF, 3=nodeB

    int tid = threadIdx.x;
    int w = tid >> 5, lane = tid & 31;
    int j = lane < HID ? lane : HID - 1;  // clamp: lanes 10..31 compute harmless garbage

    // zero-init broadcast buffer (h0 = 0)
    if (lane < 16) shH[w][lane] = 0.0f;

    // Recurrent weights for this chain, packed with gate-scales folded in:
    // rows i,f,o get x0.5 (sigmoid-from-tanh); row g x1.0. Whh row-major [4H][H].
    const float* Whh = (w == 0) ? eWhhF : (w == 1) ? eWhhB : (w == 2) ? nWhhF : nWhhB;
    unsigned long long Wif[HID], Wgo[HID];
#pragma unroll
    for (int k = 0; k < HID; k++) {
        Wif[k] = pack2(0.5f * Whh[(0 * HID + j) * HID + k],
                       0.5f * Whh[(1 * HID + j) * HID + k]);
        Wgo[k] = pack2(Whh[(2 * HID + j) * HID + k],
                       0.5f * Whh[(3 * HID + j) * HID + k]);
    }

    float h = 0.0f, c = 0.0f;

    if (w < 3) {
        const float4* pre;
        int N;
        if (w == 0)      { pre = g_preEF; N = PP * T_LEN; }           // 16384 steps
        else if (w == 1) { pre = g_preEB; N = (PP - 1) * T_LEN + 1; } // 15361 steps (p0..14 full + 1 step of p15)
        else             { pre = g_preNF; N = T_LEN; }                // 1024 steps

        // depth-3 software prefetch: load for step s+3 issues during step s.
        const float4* p0 = pre + j;
        float4 b0 = p0[0];
        float4 b1 = p0[HID];
        float4 b2 = p0[2 * HID];
        p0 += 3 * HID;
#pragma unroll 2
        for (int s = 0; s < N; s++) {
            float4 b3 = p0[0];
            p0 += HID;
            lstm_step(h, c, b0, Wif, Wgo, shH[w], lane);
            b0 = b1;
            b1 = b2;
            b2 = b3;
        }
    } else {
        // node backward: single step from zero state on x[T-1]
        float x0 = x[2 * (T_LEN - 1)], x1 = x[2 * (T_LEN - 1) + 1];
        float v0 = fmaf(nWihB[(0 * HID + j) * 2], x0, fmaf(nWihB[(0 * HID + j) * 2 + 1], x1, nbB[0 * HID + j]));
        float v1 = fmaf(nWihB[(1 * HID + j) * 2], x0, fmaf(nWihB[(1 * HID + j) * 2 + 1], x1, nbB[1 * HID + j]));
        float v2 = fmaf(nWihB[(2 * HID + j) * 2], x0, fmaf(nWihB[(2 * HID + j) * 2 + 1], x1, nbB[2 * HID + j]));
        float v3 = fmaf(nWihB[(3 * HID + j) * 2], x0, fmaf(nWihB[(3 * HID + j) * 2 + 1], x1, nbB[3 * HID + j]));
        float4 pv = make_float4(0.5f * v0, 0.5f * v1, v2, 0.5f * v3);
        lstm_step(h, c, pv, Wif, Wgo, shH[w], lane);
    }

    if (lane < HID) sh[w][lane] = h;
    __syncthreads();

    // tag[m] = lin_b[m] + sum_k (node+edge)[k] * lin_W[m][k]; only last timestep matters
    if (tid < 2) {
        float acc = linb[tid];
#pragma unroll
        for (int k = 0; k < HID; k++) {
            acc = fmaf(sh[2][k] + sh[0][k], linW[tid * 2 * HID + k], acc);          // forward halves
            acc = fmaf(sh[3][k] + sh[1][k], linW[tid * 2 * HID + HID + k], acc);    // backward halves
        }
        out[tid] = acc;
    }
}

extern "C" void kernel_launch(void* const* d_in, const int* in_sizes, int n_in,
                              void* d_out, int out_size) {
    const float* x     = (const float*)d_in[0];   // self_pose  [1,T,2]
    const float* oth   = (const float*)d_in[1];   // others_pose [1,P,T,2]
    const float* nWihF = (const float*)d_in[2];
    const float* nWhhF = (const float*)d_in[3];
    const float* nbF   = (const float*)d_in[4];
    const float* nWihB = (const float*)d_in[5];
    const float* nWhhB = (const float*)d_in[6];
    const float* nbB   = (const float*)d_in[7];
    const float* eWihF = (const float*)d_in[8];
    const float* eWhhF = (const float*)d_in[9];
    const float* ebF   = (const float*)d_in[10];
    const float* eWihB = (const float*)d_in[11];
    const float* eWhhB = (const float*)d_in[12];
    const float* ebB   = (const float*)d_in[13];
    const float* linW  = (const float*)d_in[14];
    const float* linb  = (const float*)d_in[15];

    int total = T_LEN * HID + 2 * PP * T_LEN * HID;
    precompute_kernel<<<(total + 255) / 256, 256>>>(x, oth, nWihF, nbF, eWihF, ebF, eWihB, ebB);
    seq_kernel<<<1, 128>>>(x, nWhhF, nWhhB, nWihB, nbB, eWhhF, eWhhB, linW, linb, (float*)d_out);
}